// round 7
// baseline (speedup 1.0000x reference)
#include <cuda_runtime.h>
#include <cuda_bf16.h>
#include <cstdint>
#include <cstddef>

#define NN 50000
#define EE 1250000
#define HH 64
#define DD 128
#define GG 128
#define CC 10
#define LL 2
#define NB 196            // (NN+255)/256
#define TILES64 782       // ceil(NN/64)
#define SA 72             // smem/tile row stride in bf16 elements

#define TILE_B (64 * SA * 2)                 // 9216 bytes per plane
#define NT_W 11                               // weight tiles total
#define WOFF(t, plane) ((size_t)(t) * 2 * TILE_B + (size_t)(plane) * TILE_B)

// ---------------- scratch (static __device__, no allocation) ----------------
__device__ __align__(16) float g_h[NN * HH];
__device__ __align__(16) float g_agg[NN * HH];
__device__ __align__(16) float g_pooled[GG * HH];
__device__ __align__(16) char  g_wbuf[NT_W * 2 * TILE_B];   // pre-split weights

__device__ int g_degint[NN];
__device__ int g_off[NN + 1];
__device__ int g_cursor[NN];
__device__ int g_bsum[NB];
__device__ int g_csr[EE];

// ================= CSR build =================
__global__ void zero_deg_kernel() {
    int i = blockIdx.x * blockDim.x + threadIdx.x;
    if (i < NN) g_degint[i] = 0;
}
__global__ void hist_kernel(const int* __restrict__ ei) {
    int e = blockIdx.x * blockDim.x + threadIdx.x;
    if (e < EE) atomicAdd(&g_degint[ei[EE + e]], 1);
}
__global__ void __launch_bounds__(256) scan1_kernel() {
    __shared__ int sm[256];
    int t = threadIdx.x;
    int i = blockIdx.x * 256 + t;
    int v = (i < NN) ? g_degint[i] : 0;
    sm[t] = v;
    __syncthreads();
#pragma unroll
    for (int o = 1; o < 256; o <<= 1) {
        int x = sm[t];
        if (t >= o) x += sm[t - o];
        __syncthreads();
        sm[t] = x;
        __syncthreads();
    }
    if (i < NN) g_off[i] = sm[t] - v;
    if (t == 255) g_bsum[blockIdx.x] = sm[255];
}
__global__ void __launch_bounds__(256) scan2_kernel() {
    __shared__ int sm[256];
    int t = threadIdx.x;
    int v = (t < NB) ? g_bsum[t] : 0;
    sm[t] = v;
    __syncthreads();
#pragma unroll
    for (int o = 1; o < 256; o <<= 1) {
        int x = sm[t];
        if (t >= o) x += sm[t - o];
        __syncthreads();
        sm[t] = x;
        __syncthreads();
    }
    if (t < NB) g_bsum[t] = sm[t] - v;
}
__global__ void scan3_kernel() {
    int i = blockIdx.x * blockDim.x + threadIdx.x;
    if (i < NN) {
        int o = g_off[i] + g_bsum[i >> 8];
        g_off[i] = o;
        g_cursor[i] = o;
    }
    if (i == 0) g_off[NN] = EE;
}
__global__ void fill_kernel(const int* __restrict__ ei) {
    int e = blockIdx.x * blockDim.x + threadIdx.x;
    if (e >= EE) return;
    int s = ei[e];
    int d = ei[EE + e];
    int pos = atomicAdd(&g_cursor[d], 1);
    g_csr[pos] = s;
}

// ================= aggregation (LTS-bound) =================
__global__ void __launch_bounds__(256) agg_kernel() {
    int wid = (blockIdx.x * blockDim.x + threadIdx.x) >> 5;
    if (wid >= NN) return;
    int lane = threadIdx.x & 31;
    int half = lane >> 4;
    int l16 = lane & 15;

    int lo = g_off[wid];
    int hi = g_off[wid + 1];

    float4 acc = make_float4(0.f, 0.f, 0.f, 0.f);
    for (int e = lo + half; e < hi; e += 2) {
        int s = g_csr[e];
        float4 v = *(const float4*)(g_h + (size_t)s * HH + (l16 << 2));
        acc.x += v.x; acc.y += v.y; acc.z += v.z; acc.w += v.w;
    }
    acc.x += __shfl_down_sync(0xffffffffu, acc.x, 16);
    acc.y += __shfl_down_sync(0xffffffffu, acc.y, 16);
    acc.z += __shfl_down_sync(0xffffffffu, acc.z, 16);
    acc.w += __shfl_down_sync(0xffffffffu, acc.w, 16);

    if (half == 0) {
        float inv = 1.0f / fmaxf((float)(hi - lo), 1.0f);
        acc.x *= inv; acc.y *= inv; acc.z *= inv; acc.w *= inv;
        *(float4*)(g_agg + (size_t)wid * HH + (l16 << 2)) = acc;
    }
}

// ================= bf16 split + HMMA helpers =================
__device__ __forceinline__ void split2(float a, float b, uint32_t& hi, uint32_t& lo) {
    __nv_bfloat16 ha = __float2bfloat16(a), hb = __float2bfloat16(b);
    float ra = a - __bfloat162float(ha);
    float rb = b - __bfloat162float(hb);
    __nv_bfloat16 la = __float2bfloat16(ra), lb = __float2bfloat16(rb);
    hi = (uint32_t)__bfloat16_as_ushort(ha) | ((uint32_t)__bfloat16_as_ushort(hb) << 16);
    lo = (uint32_t)__bfloat16_as_ushort(la) | ((uint32_t)__bfloat16_as_ushort(lb) << 16);
}

__device__ __forceinline__ void mma_bf16(float* acc,
                                         uint32_t a0, uint32_t a1, uint32_t a2, uint32_t a3,
                                         uint32_t b0, uint32_t b1) {
    asm volatile(
        "mma.sync.aligned.m16n8k16.row.col.f32.bf16.bf16.f32 "
        "{%0,%1,%2,%3}, {%4,%5,%6,%7}, {%8,%9}, {%0,%1,%2,%3};"
        : "+f"(acc[0]), "+f"(acc[1]), "+f"(acc[2]), "+f"(acc[3])
        : "r"(a0), "r"(a1), "r"(a2), "r"(a3), "r"(b0), "r"(b1));
}

// ================= weight pre-split (once per launch) =================
// tile t layout: plane hi/lo, element (n*SA + k) bf16, from W[(kbase+k)*64 + n]
__global__ void __launch_bounds__(256) prep_weights_kernel(
    const float* __restrict__ emb_w1, const float* __restrict__ emb_w2,
    const float* __restrict__ rel_w,  const float* __restrict__ root_w,
    const float* __restrict__ pw1,    const float* __restrict__ pw2)
{
    int t = blockIdx.x;
    const float* W;
    int kbase = 0;
    if (t == 0)      { W = emb_w1; kbase = 0;  }
    else if (t == 1) { W = emb_w1; kbase = 64; }
    else if (t == 2) { W = emb_w2; }
    else {
        int l = (t - 3) >> 2;
        int w = (t - 3) & 3;
        size_t ofs = (size_t)l * HH * HH;
        W = (w == 0) ? rel_w + ofs : (w == 1) ? root_w + ofs
          : (w == 2) ? pw1 + ofs : pw2 + ofs;
    }
    int tid = threadIdx.x;
    int n = tid >> 2;
    int kc = (tid & 3) * 16;
    uint32_t* hi = (uint32_t*)(g_wbuf + WOFF(t, 0) + (size_t)(n * SA + kc) * 2);
    uint32_t* lo = (uint32_t*)(g_wbuf + WOFF(t, 1) + (size_t)(n * SA + kc) * 2);
#pragma unroll
    for (int p = 0; p < 8; p++) {
        int k = kc + 2 * p;
        float a = W[(size_t)(kbase + k) * 64 + n];
        float b = W[(size_t)(kbase + k + 1) * 64 + n];
        uint32_t h, l;
        split2(a, b, h, l);
        hi[p] = h; lo[p] = l;
    }
}

// ================= GEMM pieces =================
// A tiles in static SMEM: 64 x SA bf16, hi + lo planes
#define OFF_AHI 0
#define OFF_ALO TILE_B

__device__ __forceinline__ void stage_A(char* sm, const float* __restrict__ A,
                                        int row0, int K, int kofs) {
    int tid = threadIdx.x;
    int r = tid >> 2;
    int c0 = (tid & 3) * 16;
    int row = row0 + r;
    float v[16];
    if (row < NN) {
        const float* src = A + (size_t)row * K + kofs + c0;
#pragma unroll
        for (int q = 0; q < 4; q++) {
            float4 f = *(const float4*)(src + q * 4);
            v[q * 4 + 0] = f.x; v[q * 4 + 1] = f.y;
            v[q * 4 + 2] = f.z; v[q * 4 + 3] = f.w;
        }
    } else {
#pragma unroll
        for (int q = 0; q < 16; q++) v[q] = 0.f;
    }
    uint32_t* hi = (uint32_t*)(sm + OFF_AHI + (size_t)(r * SA + c0) * 2);
    uint32_t* lo = (uint32_t*)(sm + OFF_ALO + (size_t)(r * SA + c0) * 2);
#pragma unroll
    for (int p = 0; p < 8; p++) {
        uint32_t h, l;
        split2(v[2 * p], v[2 * p + 1], h, l);
        hi[p] = h; lo[p] = l;
    }
}

// acc += A(64x64, smem) @ W(64x64, pre-split global tile t), warp slice 16x32
__device__ __forceinline__ void gemm_unit(const char* sm, int t,
                                          float acc[16]) {
    const char* wHi = g_wbuf + WOFF(t, 0);
    const char* wLo = g_wbuf + WOFF(t, 1);
    int lane = threadIdx.x & 31;
    int wid = threadIdx.x >> 5;
    int mt = (wid & 3) * 16;
    int nb = (wid >> 2) * 32;
    int g = lane >> 2, tg = lane & 3;
    int r0 = (mt + g) * SA;
    int r1 = (mt + g + 8) * SA;

#pragma unroll
    for (int ks = 0; ks < 4; ks++) {
        int kb = ks * 16 + tg * 2;
        uint32_t ah0 = *(const uint32_t*)(sm + OFF_AHI + (size_t)(r0 + kb) * 2);
        uint32_t ah1 = *(const uint32_t*)(sm + OFF_AHI + (size_t)(r1 + kb) * 2);
        uint32_t ah2 = *(const uint32_t*)(sm + OFF_AHI + (size_t)(r0 + kb + 8) * 2);
        uint32_t ah3 = *(const uint32_t*)(sm + OFF_AHI + (size_t)(r1 + kb + 8) * 2);
        uint32_t al0 = *(const uint32_t*)(sm + OFF_ALO + (size_t)(r0 + kb) * 2);
        uint32_t al1 = *(const uint32_t*)(sm + OFF_ALO + (size_t)(r1 + kb) * 2);
        uint32_t al2 = *(const uint32_t*)(sm + OFF_ALO + (size_t)(r0 + kb + 8) * 2);
        uint32_t al3 = *(const uint32_t*)(sm + OFF_ALO + (size_t)(r1 + kb + 8) * 2);
#pragma unroll
        for (int j = 0; j < 4; j++) {
            int nrow = (nb + j * 8 + g) * SA;
            uint32_t bh0 = *(const uint32_t*)(wHi + (size_t)(nrow + kb) * 2);
            uint32_t bh1 = *(const uint32_t*)(wHi + (size_t)(nrow + kb + 8) * 2);
            uint32_t bl0 = *(const uint32_t*)(wLo + (size_t)(nrow + kb) * 2);
            uint32_t bl1 = *(const uint32_t*)(wLo + (size_t)(nrow + kb + 8) * 2);
            mma_bf16(acc + j * 4, ah0, ah1, ah2, ah3, bh0, bh1);
            mma_bf16(acc + j * 4, ah0, ah1, ah2, ah3, bl0, bl1);
            mma_bf16(acc + j * 4, al0, al1, al2, al3, bh0, bh1);
        }
    }
}

__device__ __forceinline__ void zero16(float* a) {
#pragma unroll
    for (int i = 0; i < 16; i++) a[i] = 0.f;
}

__device__ __forceinline__ void epi_to_A(char* sm, const float acc[16],
                                         const float* __restrict__ bias, bool relu) {
    int lane = threadIdx.x & 31;
    int wid = threadIdx.x >> 5;
    int mt = (wid & 3) * 16;
    int nb = (wid >> 2) * 32;
    int g = lane >> 2, tg = lane & 3;
    int r0 = (mt + g) * SA;
    int r1 = (mt + g + 8) * SA;
#pragma unroll
    for (int j = 0; j < 4; j++) {
        int col = nb + j * 8 + tg * 2;
        float b0 = __ldg(bias + col), b1 = __ldg(bias + col + 1);
        float v00 = acc[j * 4 + 0] + b0, v01 = acc[j * 4 + 1] + b1;
        float v10 = acc[j * 4 + 2] + b0, v11 = acc[j * 4 + 3] + b1;
        if (relu) {
            v00 = fmaxf(v00, 0.f); v01 = fmaxf(v01, 0.f);
            v10 = fmaxf(v10, 0.f); v11 = fmaxf(v11, 0.f);
        }
        uint32_t h, l;
        split2(v00, v01, h, l);
        *(uint32_t*)(sm + OFF_AHI + (size_t)(r0 + col) * 2) = h;
        *(uint32_t*)(sm + OFF_ALO + (size_t)(r0 + col) * 2) = l;
        split2(v10, v11, h, l);
        *(uint32_t*)(sm + OFF_AHI + (size_t)(r1 + col) * 2) = h;
        *(uint32_t*)(sm + OFF_ALO + (size_t)(r1 + col) * 2) = l;
    }
}

__device__ __forceinline__ void epi_to_gmem(const float acc[16],
                                            const float* __restrict__ bias,
                                            bool relu, int row0) {
    int lane = threadIdx.x & 31;
    int wid = threadIdx.x >> 5;
    int mt = (wid & 3) * 16;
    int nb = (wid >> 2) * 32;
    int g = lane >> 2, tg = lane & 3;
    int ra = row0 + mt + g;
    int rb = ra + 8;
#pragma unroll
    for (int j = 0; j < 4; j++) {
        int col = nb + j * 8 + tg * 2;
        float b0 = __ldg(bias + col), b1 = __ldg(bias + col + 1);
        float v00 = acc[j * 4 + 0] + b0, v01 = acc[j * 4 + 1] + b1;
        float v10 = acc[j * 4 + 2] + b0, v11 = acc[j * 4 + 3] + b1;
        if (relu) {
            v00 = fmaxf(v00, 0.f); v01 = fmaxf(v01, 0.f);
            v10 = fmaxf(v10, 0.f); v11 = fmaxf(v11, 0.f);
        }
        if (ra < NN) *(float2*)(g_h + (size_t)ra * 64 + col) = make_float2(v00, v01);
        if (rb < NN) *(float2*)(g_h + (size_t)rb * 64 + col) = make_float2(v10, v11);
    }
}

// ================= fused embed MLP =================
__global__ void __launch_bounds__(256) embed_kernel(
    const float* __restrict__ x,
    const float* __restrict__ b1, const float* __restrict__ b2)
{
    __shared__ __align__(16) char sm[2 * TILE_B];
    int row0 = blockIdx.x * 64;

    stage_A(sm, x, row0, DD, 0);
    __syncthreads();

    float acc[16];
    zero16(acc);
    gemm_unit(sm, 0, acc);                 // x[:,0:64]  @ W1[0:64]
    __syncthreads();
    stage_A(sm, x, row0, DD, 64);
    __syncthreads();
    gemm_unit(sm, 1, acc);                 // += x[:,64:128] @ W1[64:128]
    __syncthreads();
    epi_to_A(sm, acc, b1, true);           // t = relu(.+b1)
    __syncthreads();

    zero16(acc);
    gemm_unit(sm, 2, acc);                 // t @ W2
    epi_to_gmem(acc, b2, false, row0);     // h = . + b2
}

// ================= fused conv layer =================
__global__ void __launch_bounds__(256) layer_kernel(
    int t0,
    const float* __restrict__ rb,
    const float* __restrict__ pb1,
    const float* __restrict__ pb2)
{
    __shared__ __align__(16) char sm[2 * TILE_B];
    int row0 = blockIdx.x * 64;

    stage_A(sm, g_agg, row0, HH, 0);
    __syncthreads();

    float acc[16];
    zero16(acc);
    gemm_unit(sm, t0 + 0, acc);            // agg @ rel
    __syncthreads();
    stage_A(sm, g_h, row0, HH, 0);
    __syncthreads();
    gemm_unit(sm, t0 + 1, acc);            // += h @ root
    __syncthreads();
    epi_to_A(sm, acc, rb, false);          // h2 = . + rb
    __syncthreads();

    zero16(acc);
    gemm_unit(sm, t0 + 2, acc);            // h2 @ pw1
    __syncthreads();
    epi_to_A(sm, acc, pb1, true);          // t = relu(.+pb1)
    __syncthreads();

    zero16(acc);
    gemm_unit(sm, t0 + 3, acc);            // t @ pw2
    epi_to_gmem(acc, pb2, true, row0);     // h = relu(.+pb2)
}

// ================= pooling + classifier =================
__device__ __forceinline__ int lbound(const int* a, int n, int v) {
    int lo = 0, hi = n;
    while (lo < hi) {
        int m = (lo + hi) >> 1;
        if (a[m] < v) lo = m + 1; else hi = m;
    }
    return lo;
}

__global__ void __launch_bounds__(256) pool_kernel(const int* __restrict__ batch) {
    __shared__ int s_lo, s_hi;
    __shared__ float sm[4][64];
    int g = blockIdx.x;
    int tid = threadIdx.x;
    if (tid == 0) {
        s_lo = lbound(batch, NN, g);
        s_hi = lbound(batch, NN, g + 1);
    }
    __syncthreads();
    int lo = s_lo, hi = s_hi;
    int col = tid & 63;
    int rg = tid >> 6;

    float acc = 0.f;
    for (int n = lo + rg; n < hi; n += 4)
        acc += g_h[(size_t)n * HH + col];
    sm[rg][col] = acc;
    __syncthreads();
    if (rg == 0) {
        float s = sm[0][col] + sm[1][col] + sm[2][col] + sm[3][col];
        float inv = 1.0f / fmaxf((float)(hi - lo), 1.0f);
        g_pooled[(size_t)g * HH + col] = s * inv;
    }
}

__global__ void cls_kernel(const float* __restrict__ W,
                           const float* __restrict__ b,
                           float* __restrict__ out)
{
    int tid = blockIdx.x * blockDim.x + threadIdx.x;
    if (tid >= GG * CC) return;
    int g = tid / CC;
    int c = tid % CC;
    float s = b[c];
#pragma unroll
    for (int k = 0; k < HH; k++)
        s += g_pooled[g * HH + k] * W[k * CC + c];
    out[tid] = s;
}

// ================= launcher =================
extern "C" void kernel_launch(void* const* d_in, const int* in_sizes, int n_in,
                              void* d_out, int out_size) {
    const float* x       = (const float*)d_in[0];
    const int*   ei      = (const int*)d_in[1];
    const int*   batch   = (const int*)d_in[2];
    const float* emb_w1  = (const float*)d_in[3];
    const float* emb_b1  = (const float*)d_in[4];
    const float* emb_w2  = (const float*)d_in[5];
    const float* emb_b2  = (const float*)d_in[6];
    const float* rel_w   = (const float*)d_in[7];
    const float* rel_b   = (const float*)d_in[8];
    const float* root_w  = (const float*)d_in[9];
    const float* post_w1 = (const float*)d_in[10];
    const float* post_b1 = (const float*)d_in[11];
    const float* post_w2 = (const float*)d_in[12];
    const float* post_b2 = (const float*)d_in[13];
    const float* cls_w   = (const float*)d_in[14];
    const float* cls_b   = (const float*)d_in[15];
    float*       out     = (float*)d_out;

    const int TB = 256;

    // ---- weight pre-split + CSR build ----
    prep_weights_kernel<<<NT_W, 256>>>(emb_w1, emb_w2, rel_w, root_w, post_w1, post_w2);
    zero_deg_kernel<<<(NN + TB - 1) / TB, TB>>>();
    hist_kernel<<<(EE + TB - 1) / TB, TB>>>(ei);
    scan1_kernel<<<NB, 256>>>();
    scan2_kernel<<<1, 256>>>();
    scan3_kernel<<<(NN + TB - 1) / TB, TB>>>();
    fill_kernel<<<(EE + TB - 1) / TB, TB>>>(ei);

    // ---- embed MLP ----
    embed_kernel<<<TILES64, 256>>>(x, emb_b1, emb_b2);

    for (int l = 0; l < LL; l++) {
        agg_kernel<<<(NN * 32 + TB - 1) / TB, TB>>>();
        layer_kernel<<<TILES64, 256>>>(
            3 + 4 * l,
            rel_b   + (size_t)l * HH,
            post_b1 + (size_t)l * HH,
            post_b2 + (size_t)l * HH);
    }

    // ---- mean pool + classifier ----
    pool_kernel<<<GG, 256>>>(batch);
    cls_kernel<<<(GG * CC + TB - 1) / TB, TB>>>(cls_w, cls_b, out);
}

// round 8
// speedup vs baseline: 1.0224x; 1.0224x over previous
#include <cuda_runtime.h>
#include <cuda_bf16.h>
#include <cstdint>
#include <cstddef>

#define NN 50000
#define EE 1250000
#define HH 64
#define DD 128
#define GG 128
#define CC 10
#define LL 2
#define NB 196            // (NN+255)/256
#define TILES64 782       // ceil(NN/64)
#define SA 72             // row stride in bf16 elements (conflict-free LDS)

#define TILE_B (64 * SA * 2)                 // 9216 bytes per plane
#define NT_W 11                              // weight tiles total
#define ZB 25                                // zeroing blocks appended to prep grid
#define WOFF(t, plane) ((size_t)(t) * 2 * TILE_B + (size_t)(plane) * TILE_B)

// ---------------- scratch (static __device__, no allocation) ----------------
__device__ __align__(16) float g_h[NN * HH];
__device__ __align__(16) float g_agg[NN * HH];
__device__ __align__(16) float g_pooled[GG * HH];
__device__ __align__(16) char  g_wbuf[NT_W * 2 * TILE_B];   // pre-split weights

__device__ int g_degint[NN];
__device__ int g_off[NN + 1];
__device__ int g_cursor[NN];
__device__ int g_bsum[NB];
__device__ int g_csr[EE];

// ================= bf16 split + HMMA helpers =================
__device__ __forceinline__ void split2(float a, float b, uint32_t& hi, uint32_t& lo) {
    __nv_bfloat16 ha = __float2bfloat16(a), hb = __float2bfloat16(b);
    float ra = a - __bfloat162float(ha);
    float rb = b - __bfloat162float(hb);
    __nv_bfloat16 la = __float2bfloat16(ra), lb = __float2bfloat16(rb);
    hi = (uint32_t)__bfloat16_as_ushort(ha) | ((uint32_t)__bfloat16_as_ushort(hb) << 16);
    lo = (uint32_t)__bfloat16_as_ushort(la) | ((uint32_t)__bfloat16_as_ushort(lb) << 16);
}

__device__ __forceinline__ void mma_bf16(float* acc,
                                         uint32_t a0, uint32_t a1, uint32_t a2, uint32_t a3,
                                         uint32_t b0, uint32_t b1) {
    asm volatile(
        "mma.sync.aligned.m16n8k16.row.col.f32.bf16.bf16.f32 "
        "{%0,%1,%2,%3}, {%4,%5,%6,%7}, {%8,%9}, {%0,%1,%2,%3};"
        : "+f"(acc[0]), "+f"(acc[1]), "+f"(acc[2]), "+f"(acc[3])
        : "r"(a0), "r"(a1), "r"(a2), "r"(a3), "r"(b0), "r"(b1));
}

// ================= weight pre-split + degree zero (once per launch) =========
__global__ void __launch_bounds__(256) prep_kernel(
    const float* __restrict__ emb_w1, const float* __restrict__ emb_w2,
    const float* __restrict__ rel_w,  const float* __restrict__ root_w,
    const float* __restrict__ pw1,    const float* __restrict__ pw2)
{
    int t = blockIdx.x;
    if (t >= NT_W) {
        int z = t - NT_W;
        int base = z * 2000;
        for (int i = threadIdx.x; i < 2000; i += 256) {
            int idx = base + i;
            if (idx < NN) g_degint[idx] = 0;
        }
        return;
    }
    const float* W;
    int kbase = 0;
    if (t == 0)      { W = emb_w1; kbase = 0;  }
    else if (t == 1) { W = emb_w1; kbase = 64; }
    else if (t == 2) { W = emb_w2; }
    else {
        int l = (t - 3) >> 2;
        int w = (t - 3) & 3;
        size_t ofs = (size_t)l * HH * HH;
        W = (w == 0) ? rel_w + ofs : (w == 1) ? root_w + ofs
          : (w == 2) ? pw1 + ofs : pw2 + ofs;
    }
    int tid = threadIdx.x;
    int n = tid >> 2;
    int kc = (tid & 3) * 16;
    uint32_t* hi = (uint32_t*)(g_wbuf + WOFF(t, 0) + (size_t)(n * SA + kc) * 2);
    uint32_t* lo = (uint32_t*)(g_wbuf + WOFF(t, 1) + (size_t)(n * SA + kc) * 2);
#pragma unroll
    for (int p = 0; p < 8; p++) {
        int k = kc + 2 * p;
        float a = W[(size_t)(kbase + k) * 64 + n];
        float b = W[(size_t)(kbase + k + 1) * 64 + n];
        uint32_t h, l;
        split2(a, b, h, l);
        hi[p] = h; lo[p] = l;
    }
}

// ================= CSR build =================
__global__ void hist_kernel(const int* __restrict__ ei) {
    int e = blockIdx.x * blockDim.x + threadIdx.x;
    if (e < EE) atomicAdd(&g_degint[ei[EE + e]], 1);
}
__global__ void __launch_bounds__(256) scan1_kernel() {
    __shared__ int sm[256];
    int t = threadIdx.x;
    int i = blockIdx.x * 256 + t;
    int v = (i < NN) ? g_degint[i] : 0;
    sm[t] = v;
    __syncthreads();
#pragma unroll
    for (int o = 1; o < 256; o <<= 1) {
        int x = sm[t];
        if (t >= o) x += sm[t - o];
        __syncthreads();
        sm[t] = x;
        __syncthreads();
    }
    if (i < NN) g_off[i] = sm[t] - v;
    if (t == 255) g_bsum[blockIdx.x] = sm[255];
}
__global__ void __launch_bounds__(256) scan2_kernel() {
    __shared__ int sm[256];
    int t = threadIdx.x;
    int v = (t < NB) ? g_bsum[t] : 0;
    sm[t] = v;
    __syncthreads();
#pragma unroll
    for (int o = 1; o < 256; o <<= 1) {
        int x = sm[t];
        if (t >= o) x += sm[t - o];
        __syncthreads();
        sm[t] = x;
        __syncthreads();
    }
    if (t < NB) g_bsum[t] = sm[t] - v;
}
__global__ void scan3_kernel() {
    int i = blockIdx.x * blockDim.x + threadIdx.x;
    if (i < NN) {
        int o = g_off[i] + g_bsum[i >> 8];
        g_off[i] = o;
        g_cursor[i] = o;
    }
    if (i == 0) g_off[NN] = EE;
}
__global__ void fill_kernel(const int* __restrict__ ei) {
    int e = blockIdx.x * blockDim.x + threadIdx.x;
    if (e >= EE) return;
    int s = ei[e];
    int d = ei[EE + e];
    int pos = atomicAdd(&g_cursor[d], 1);
    g_csr[pos] = s;
}

// ================= aggregation (LTS-bound) =================
__global__ void __launch_bounds__(256) agg_kernel() {
    int wid = (blockIdx.x * blockDim.x + threadIdx.x) >> 5;
    if (wid >= NN) return;
    int lane = threadIdx.x & 31;
    int half = lane >> 4;
    int l16 = lane & 15;

    int lo = g_off[wid];
    int hi = g_off[wid + 1];

    float4 acc = make_float4(0.f, 0.f, 0.f, 0.f);
    for (int e = lo + half; e < hi; e += 2) {
        int s = g_csr[e];
        float4 v = *(const float4*)(g_h + (size_t)s * HH + (l16 << 2));
        acc.x += v.x; acc.y += v.y; acc.z += v.z; acc.w += v.w;
    }
    acc.x += __shfl_down_sync(0xffffffffu, acc.x, 16);
    acc.y += __shfl_down_sync(0xffffffffu, acc.y, 16);
    acc.z += __shfl_down_sync(0xffffffffu, acc.z, 16);
    acc.w += __shfl_down_sync(0xffffffffu, acc.w, 16);

    if (half == 0) {
        float inv = 1.0f / fmaxf((float)(hi - lo), 1.0f);
        acc.x *= inv; acc.y *= inv; acc.z *= inv; acc.w *= inv;
        *(float4*)(g_agg + (size_t)wid * HH + (l16 << 2)) = acc;
    }
}

// ================= GEMM pieces =================
// dynamic smem: [A hi][A lo][weight tiles (verbatim copy of g_wbuf range)]
#define OFF_AHI 0
#define OFF_ALO TILE_B
#define OFF_W   (2 * TILE_B)
// within-smem tile i (relative to copied base): hi at OFF_W + i*2*TILE_B

__device__ __forceinline__ void stage_A(char* sm, const float* __restrict__ A,
                                        int row0, int K, int kofs) {
    int tid = threadIdx.x;
    int r = tid >> 2;
    int c0 = (tid & 3) * 16;
    int row = row0 + r;
    float v[16];
    if (row < NN) {
        const float* src = A + (size_t)row * K + kofs + c0;
#pragma unroll
        for (int q = 0; q < 4; q++) {
            float4 f = *(const float4*)(src + q * 4);
            v[q * 4 + 0] = f.x; v[q * 4 + 1] = f.y;
            v[q * 4 + 2] = f.z; v[q * 4 + 3] = f.w;
        }
    } else {
#pragma unroll
        for (int q = 0; q < 16; q++) v[q] = 0.f;
    }
    uint32_t* hi = (uint32_t*)(sm + OFF_AHI + (size_t)(r * SA + c0) * 2);
    uint32_t* lo = (uint32_t*)(sm + OFF_ALO + (size_t)(r * SA + c0) * 2);
#pragma unroll
    for (int p = 0; p < 8; p++) {
        uint32_t h, l;
        split2(v[2 * p], v[2 * p + 1], h, l);
        hi[p] = h; lo[p] = l;
    }
}

// bulk copy of nt weight tile-pairs (g_wbuf tiles t0..t0+nt-1) into smem at OFF_W
__device__ __forceinline__ void copy_W(char* sm, int t0, int nt) {
    const float4* src = (const float4*)(g_wbuf + WOFF(t0, 0));
    float4* dst = (float4*)(sm + OFF_W);
    int n = nt * 2 * TILE_B / 16;
    for (int i = threadIdx.x; i < n; i += 256)
        dst[i] = src[i];
}

// acc += A(64x64, smem) @ W(tile i in smem), warp slice 16x32
__device__ __forceinline__ void gemm_unit(const char* sm, int i, float acc[16]) {
    const char* wHi = sm + OFF_W + (size_t)i * 2 * TILE_B;
    const char* wLo = wHi + TILE_B;
    int lane = threadIdx.x & 31;
    int wid = threadIdx.x >> 5;
    int mt = (wid & 3) * 16;
    int nb = (wid >> 2) * 32;
    int g = lane >> 2, tg = lane & 3;
    int r0 = (mt + g) * SA;
    int r1 = (mt + g + 8) * SA;

#pragma unroll
    for (int ks = 0; ks < 4; ks++) {
        int kb = ks * 16 + tg * 2;
        uint32_t ah0 = *(const uint32_t*)(sm + OFF_AHI + (size_t)(r0 + kb) * 2);
        uint32_t ah1 = *(const uint32_t*)(sm + OFF_AHI + (size_t)(r1 + kb) * 2);
        uint32_t ah2 = *(const uint32_t*)(sm + OFF_AHI + (size_t)(r0 + kb + 8) * 2);
        uint32_t ah3 = *(const uint32_t*)(sm + OFF_AHI + (size_t)(r1 + kb + 8) * 2);
        uint32_t al0 = *(const uint32_t*)(sm + OFF_ALO + (size_t)(r0 + kb) * 2);
        uint32_t al1 = *(const uint32_t*)(sm + OFF_ALO + (size_t)(r1 + kb) * 2);
        uint32_t al2 = *(const uint32_t*)(sm + OFF_ALO + (size_t)(r0 + kb + 8) * 2);
        uint32_t al3 = *(const uint32_t*)(sm + OFF_ALO + (size_t)(r1 + kb + 8) * 2);
#pragma unroll
        for (int j = 0; j < 4; j++) {
            int nrow = (nb + j * 8 + g) * SA;
            uint32_t bh0 = *(const uint32_t*)(wHi + (size_t)(nrow + kb) * 2);
            uint32_t bh1 = *(const uint32_t*)(wHi + (size_t)(nrow + kb + 8) * 2);
            uint32_t bl0 = *(const uint32_t*)(wLo + (size_t)(nrow + kb) * 2);
            uint32_t bl1 = *(const uint32_t*)(wLo + (size_t)(nrow + kb + 8) * 2);
            mma_bf16(acc + j * 4, ah0, ah1, ah2, ah3, bh0, bh1);
            mma_bf16(acc + j * 4, ah0, ah1, ah2, ah3, bl0, bl1);
            mma_bf16(acc + j * 4, al0, al1, al2, al3, bh0, bh1);
        }
    }
}

__device__ __forceinline__ void zero16(float* a) {
#pragma unroll
    for (int i = 0; i < 16; i++) a[i] = 0.f;
}

__device__ __forceinline__ void epi_to_A(char* sm, const float acc[16],
                                         const float* __restrict__ bias, bool relu) {
    int lane = threadIdx.x & 31;
    int wid = threadIdx.x >> 5;
    int mt = (wid & 3) * 16;
    int nb = (wid >> 2) * 32;
    int g = lane >> 2, tg = lane & 3;
    int r0 = (mt + g) * SA;
    int r1 = (mt + g + 8) * SA;
#pragma unroll
    for (int j = 0; j < 4; j++) {
        int col = nb + j * 8 + tg * 2;
        float b0 = __ldg(bias + col), b1 = __ldg(bias + col + 1);
        float v00 = acc[j * 4 + 0] + b0, v01 = acc[j * 4 + 1] + b1;
        float v10 = acc[j * 4 + 2] + b0, v11 = acc[j * 4 + 3] + b1;
        if (relu) {
            v00 = fmaxf(v00, 0.f); v01 = fmaxf(v01, 0.f);
            v10 = fmaxf(v10, 0.f); v11 = fmaxf(v11, 0.f);
        }
        uint32_t h, l;
        split2(v00, v01, h, l);
        *(uint32_t*)(sm + OFF_AHI + (size_t)(r0 + col) * 2) = h;
        *(uint32_t*)(sm + OFF_ALO + (size_t)(r0 + col) * 2) = l;
        split2(v10, v11, h, l);
        *(uint32_t*)(sm + OFF_AHI + (size_t)(r1 + col) * 2) = h;
        *(uint32_t*)(sm + OFF_ALO + (size_t)(r1 + col) * 2) = l;
    }
}

__device__ __forceinline__ void epi_to_gmem(const float acc[16],
                                            const float* __restrict__ bias,
                                            bool relu, int row0) {
    int lane = threadIdx.x & 31;
    int wid = threadIdx.x >> 5;
    int mt = (wid & 3) * 16;
    int nb = (wid >> 2) * 32;
    int g = lane >> 2, tg = lane & 3;
    int ra = row0 + mt + g;
    int rb = ra + 8;
#pragma unroll
    for (int j = 0; j < 4; j++) {
        int col = nb + j * 8 + tg * 2;
        float b0 = __ldg(bias + col), b1 = __ldg(bias + col + 1);
        float v00 = acc[j * 4 + 0] + b0, v01 = acc[j * 4 + 1] + b1;
        float v10 = acc[j * 4 + 2] + b0, v11 = acc[j * 4 + 3] + b1;
        if (relu) {
            v00 = fmaxf(v00, 0.f); v01 = fmaxf(v01, 0.f);
            v10 = fmaxf(v10, 0.f); v11 = fmaxf(v11, 0.f);
        }
        if (ra < NN) *(float2*)(g_h + (size_t)ra * 64 + col) = make_float2(v00, v01);
        if (rb < NN) *(float2*)(g_h + (size_t)rb * 64 + col) = make_float2(v10, v11);
    }
}

// ================= fused embed MLP =================
__global__ void __launch_bounds__(256) embed_kernel(
    const float* __restrict__ x,
    const float* __restrict__ b1, const float* __restrict__ b2)
{
    extern __shared__ __align__(16) char sm[];
    int row0 = blockIdx.x * 64;

    copy_W(sm, 0, 3);                      // tiles 0,1,2
    stage_A(sm, x, row0, DD, 0);
    __syncthreads();

    float acc[16];
    zero16(acc);
    gemm_unit(sm, 0, acc);                 // x[:,0:64]  @ W1[0:64]
    __syncthreads();
    stage_A(sm, x, row0, DD, 64);
    __syncthreads();
    gemm_unit(sm, 1, acc);                 // += x[:,64:128] @ W1[64:128]
    __syncthreads();
    epi_to_A(sm, acc, b1, true);           // t = relu(.+b1)
    __syncthreads();

    zero16(acc);
    gemm_unit(sm, 2, acc);                 // t @ W2
    epi_to_gmem(acc, b2, false, row0);     // h = . + b2
}

// ================= fused conv layer =================
__global__ void __launch_bounds__(256) layer_kernel(
    int t0,
    const float* __restrict__ rb,
    const float* __restrict__ pb1,
    const float* __restrict__ pb2)
{
    extern __shared__ __align__(16) char sm[];
    int row0 = blockIdx.x * 64;

    copy_W(sm, t0, 4);                     // rel, root, pw1, pw2
    stage_A(sm, g_agg, row0, HH, 0);
    __syncthreads();

    float acc[16];
    zero16(acc);
    gemm_unit(sm, 0, acc);                 // agg @ rel
    __syncthreads();
    stage_A(sm, g_h, row0, HH, 0);
    __syncthreads();
    gemm_unit(sm, 1, acc);                 // += h @ root
    __syncthreads();
    epi_to_A(sm, acc, rb, false);          // h2 = . + rb
    __syncthreads();

    zero16(acc);
    gemm_unit(sm, 2, acc);                 // h2 @ pw1
    __syncthreads();
    epi_to_A(sm, acc, pb1, true);          // t = relu(.+pb1)
    __syncthreads();

    zero16(acc);
    gemm_unit(sm, 3, acc);                 // t @ pw2
    epi_to_gmem(acc, pb2, true, row0);     // h = relu(.+pb2)
}

// ================= pooling + classifier =================
__device__ __forceinline__ int lbound(const int* a, int n, int v) {
    int lo = 0, hi = n;
    while (lo < hi) {
        int m = (lo + hi) >> 1;
        if (a[m] < v) lo = m + 1; else hi = m;
    }
    return lo;
}

__global__ void __launch_bounds__(256) pool_kernel(const int* __restrict__ batch) {
    __shared__ int s_lo, s_hi;
    __shared__ float sm[4][64];
    int g = blockIdx.x;
    int tid = threadIdx.x;
    if (tid == 0) {
        s_lo = lbound(batch, NN, g);
        s_hi = lbound(batch, NN, g + 1);
    }
    __syncthreads();
    int lo = s_lo, hi = s_hi;
    int col = tid & 63;
    int rg = tid >> 6;

    float acc = 0.f;
    for (int n = lo + rg; n < hi; n += 4)
        acc += g_h[(size_t)n * HH + col];
    sm[rg][col] = acc;
    __syncthreads();
    if (rg == 0) {
        float s = sm[0][col] + sm[1][col] + sm[2][col] + sm[3][col];
        float inv = 1.0f / fmaxf((float)(hi - lo), 1.0f);
        g_pooled[(size_t)g * HH + col] = s * inv;
    }
}

__global__ void cls_kernel(const float* __restrict__ W,
                           const float* __restrict__ b,
                           float* __restrict__ out)
{
    int tid = blockIdx.x * blockDim.x + threadIdx.x;
    if (tid >= GG * CC) return;
    int g = tid / CC;
    int c = tid % CC;
    float s = b[c];
#pragma unroll
    for (int k = 0; k < HH; k++)
        s += g_pooled[g * HH + k] * W[k * CC + c];
    out[tid] = s;
}

// ================= launcher =================
extern "C" void kernel_launch(void* const* d_in, const int* in_sizes, int n_in,
                              void* d_out, int out_size) {
    const float* x       = (const float*)d_in[0];
    const int*   ei      = (const int*)d_in[1];
    const int*   batch   = (const int*)d_in[2];
    const float* emb_w1  = (const float*)d_in[3];
    const float* emb_b1  = (const float*)d_in[4];
    const float* emb_w2  = (const float*)d_in[5];
    const float* emb_b2  = (const float*)d_in[6];
    const float* rel_w   = (const float*)d_in[7];
    const float* rel_b   = (const float*)d_in[8];
    const float* root_w  = (const float*)d_in[9];
    const float* post_w1 = (const float*)d_in[10];
    const float* post_b1 = (const float*)d_in[11];
    const float* post_w2 = (const float*)d_in[12];
    const float* post_b2 = (const float*)d_in[13];
    const float* cls_w   = (const float*)d_in[14];
    const float* cls_b   = (const float*)d_in[15];
    float*       out     = (float*)d_out;

    const int TB = 256;
    const int embed_smem = 2 * TILE_B + 3 * 2 * TILE_B;   // 73,728 B
    const int layer_smem = 2 * TILE_B + 4 * 2 * TILE_B;   // 92,160 B
    cudaFuncSetAttribute(embed_kernel, cudaFuncAttributeMaxDynamicSharedMemorySize, embed_smem);
    cudaFuncSetAttribute(layer_kernel, cudaFuncAttributeMaxDynamicSharedMemorySize, layer_smem);

    // ---- weight pre-split (+ degree zero) + CSR build ----
    prep_kernel<<<NT_W + ZB, 256>>>(emb_w1, emb_w2, rel_w, root_w, post_w1, post_w2);
    hist_kernel<<<(EE + TB - 1) / TB, TB>>>(ei);
    scan1_kernel<<<NB, 256>>>();
    scan2_kernel<<<1, 256>>>();
    scan3_kernel<<<(NN + TB - 1) / TB, TB>>>();
    fill_kernel<<<(EE + TB - 1) / TB, TB>>>(ei);

    // ---- embed MLP ----
    embed_kernel<<<TILES64, 256, embed_smem>>>(x, emb_b1, emb_b2);

    for (int l = 0; l < LL; l++) {
        agg_kernel<<<(NN * 32 + TB - 1) / TB, TB>>>();
        layer_kernel<<<TILES64, 256, layer_smem>>>(
            3 + 4 * l,
            rel_b   + (size_t)l * HH,
            post_b1 + (size_t)l * HH,
            post_b2 + (size_t)l * HH);
    }

    // ---- mean pool + classifier ----
    pool_kernel<<<GG, 256>>>(batch);
    cls_kernel<<<(GG * CC + TB - 1) / TB, TB>>>(cls_w, cls_b, out);
}